// round 14
// baseline (speedup 1.0000x reference)
#include <cuda_runtime.h>
#include <cuda_bf16.h>
#include <cstdint>

// Problem constants
#define Bc 8
#define Sq 2048
#define Ec 512
#define Hc 8
#define Dc 64
#define Mrows (Bc * Sq)   // 16384

#define LOG2E 1.4426950408889634f

// Scratch (no cudaMalloc allowed)
__device__ float g_Q[(size_t)Mrows * Ec];
__device__ float g_K[(size_t)Mrows * Ec];
__device__ float g_V[(size_t)Mrows * Ec];
__device__ float g_C[(size_t)Mrows * Ec];
__device__ float g_T3[(size_t)3 * Mrows * Ec];   // tf32-rounded q/k/v inputs
__device__ float g_WT4[(size_t)4 * Ec * Ec];     // tf32-rounded wq/wk/wv/wo

// ---------------------------------------------------------------------------
// helpers
// ---------------------------------------------------------------------------
__device__ __forceinline__ uint32_t f2t(float x) {
    uint32_t u;
    asm("cvt.rna.tf32.f32 %0, %1;" : "=r"(u) : "f"(x));
    return u;
}

__device__ __forceinline__ void mma_tf32(float c[4],
    uint32_t a0, uint32_t a1, uint32_t a2, uint32_t a3,
    uint32_t b0, uint32_t b1)
{
    asm volatile(
        "mma.sync.aligned.m16n8k8.row.col.f32.tf32.tf32.f32 "
        "{%0,%1,%2,%3}, {%4,%5,%6,%7}, {%8,%9}, {%0,%1,%2,%3};"
        : "+f"(c[0]), "+f"(c[1]), "+f"(c[2]), "+f"(c[3])
        : "r"(a0), "r"(a1), "r"(a2), "r"(a3), "r"(b0), "r"(b1));
}

__device__ __forceinline__ uint32_t s2u(const void* p) {
    uint32_t a;
    asm("{ .reg .u64 t; cvta.to.shared.u64 t, %1; cvt.u32.u64 %0, t; }"
        : "=r"(a) : "l"(p));
    return a;
}

__device__ __forceinline__ void cpasync16(uint32_t dst, const void* src) {
    asm volatile("cp.async.cg.shared.global [%0], [%1], 16;" :: "r"(dst), "l"(src));
}
#define CP_COMMIT() asm volatile("cp.async.commit_group;" ::: "memory")
#define CP_WAIT(n)  asm volatile("cp.async.wait_group %0;" :: "n"(n) : "memory")

// ---------------------------------------------------------------------------
// merged tf32 rounding: 3 activation inputs -> g_T3
// ---------------------------------------------------------------------------
__global__ __launch_bounds__(256) void conv3(
    const float* __restrict__ a0, const float* __restrict__ a1,
    const float* __restrict__ a2, float* __restrict__ y, int n4)
{
    int i = blockIdx.x * 256 + threadIdx.x;
    if (i >= 3 * n4) return;
    int which = i / n4;
    int j = i - which * n4;
    const float* src = which == 0 ? a0 : (which == 1 ? a1 : a2);
    float4 v = ((const float4*)src)[j];
    ((uint4*)y)[i] = make_uint4(f2t(v.x), f2t(v.y), f2t(v.z), f2t(v.w));
}

// merged tf32 rounding: 4 weight matrices -> g_WT4
__global__ __launch_bounds__(256) void convW4(
    const float* __restrict__ w0, const float* __restrict__ w1,
    const float* __restrict__ w2, const float* __restrict__ w3,
    float* __restrict__ y, int n4)
{
    int i = blockIdx.x * 256 + threadIdx.x;
    if (i >= 4 * n4) return;
    int which = i / n4;
    int j = i - which * n4;
    const float* src = which == 0 ? w0 : (which == 1 ? w1 : (which == 2 ? w2 : w3));
    float4 v = ((const float4*)src)[j];
    ((uint4*)y)[i] = make_uint4(f2t(v.x), f2t(v.y), f2t(v.z), f2t(v.w));
}

// ---------------------------------------------------------------------------
// tf32 GEMM: C = round_tf32((A @ W + bias) * scale)
// Batched over gridDim.z = 3 (Q/K/V projections) or single (output proj).
// CTA tile 128x128, Bk=32, double-buffered cp.async.
// 8 warps = 2(m) x 4(n); warp tile 64x32 = 4 m16 x 4 n8.
// ---------------------------------------------------------------------------
#define APITCH 36
#define BPITCH 136
#define ASTG (128 * APITCH * 4)     // 18432 B
#define BSTG (32 * BPITCH * 4)      // 17408 B
#define GSTG (ASTG + BSTG)          // 35840 B
#define GSMEM (2 * GSTG)            // 71680 B

__global__ __launch_bounds__(256) void gemm_tf32_qkv(
    const float* __restrict__ A3, const float* __restrict__ W4,
    const float* __restrict__ bq, const float* __restrict__ bk,
    const float* __restrict__ bv,
    float* __restrict__ Qo, float* __restrict__ Ko, float* __restrict__ Vo)
{
    extern __shared__ __align__(16) uint8_t smem[];
    const uint32_t sb = s2u(smem);

    const int tid  = threadIdx.x;
    const int lane = tid & 31;
    const int w    = tid >> 5;
    const int wm   = w >> 2;
    const int wn   = w & 3;
    const int g    = lane >> 2;
    const int t    = lane & 3;
    const int m0   = blockIdx.y * 128;
    const int n0   = blockIdx.x * 128;
    const int z    = blockIdx.z;

    const float* bias = z == 0 ? bq : (z == 1 ? bk : bv);
    float* C          = z == 0 ? Qo : (z == 1 ? Ko : Vo);
    const float scale = z == 0 ? 0.125f * LOG2E : 1.0f;

    const char* Ab = (const char*)(A3 + (size_t)z * Mrows * Ec) + (size_t)m0 * Ec * 4;
    const char* Wb = (const char*)(W4 + (size_t)z * Ec * Ec) + (size_t)n0 * 4;

    auto fill = [&](int s) {
        uint32_t base = sb + (uint32_t)(s & 1) * GSTG;
        #pragma unroll
        for (int q = 0; q < 4; ++q) {
            int i = q * 256 + tid;
            int r = i >> 3, c = i & 7;
            cpasync16(base + (uint32_t)(r * (APITCH * 4) + c * 16),
                      Ab + (size_t)r * (Ec * 4) + s * 128 + c * 16);
        }
        #pragma unroll
        for (int q = 0; q < 4; ++q) {
            int i = q * 256 + tid;
            int r = i >> 5, c = i & 31;
            cpasync16(base + ASTG + (uint32_t)(r * (BPITCH * 4) + c * 16),
                      Wb + (size_t)(s * 32 + r) * (Ec * 4) + c * 16);
        }
        CP_COMMIT();
    };

    float acc[4][4][4] = {};
    fill(0);

    for (int s = 0; s < 16; ++s) {
        if (s < 15) {
            fill(s + 1);
            CP_WAIT(1);
        } else {
            CP_WAIT(0);
        }
        __syncthreads();

        const uint8_t* buf = smem + (s & 1) * GSTG;
        const uint32_t* As = (const uint32_t*)buf;
        const uint32_t* Ws = (const uint32_t*)(buf + ASTG);

        #pragma unroll
        for (int k8 = 0; k8 < 4; ++k8) {
            uint32_t a[4][4];
            #pragma unroll
            for (int mt = 0; mt < 4; ++mt) {
                int m = wm * 64 + mt * 16;
                a[mt][0] = As[(m + g    ) * APITCH + k8 * 8 + t];
                a[mt][1] = As[(m + g + 8) * APITCH + k8 * 8 + t];
                a[mt][2] = As[(m + g    ) * APITCH + k8 * 8 + t + 4];
                a[mt][3] = As[(m + g + 8) * APITCH + k8 * 8 + t + 4];
            }
            #pragma unroll
            for (int nt = 0; nt < 4; ++nt) {
                uint32_t b0 = Ws[(k8 * 8 + t    ) * BPITCH + wn * 32 + nt * 8 + g];
                uint32_t b1 = Ws[(k8 * 8 + t + 4) * BPITCH + wn * 32 + nt * 8 + g];
                #pragma unroll
                for (int mt = 0; mt < 4; ++mt)
                    mma_tf32(acc[mt][nt], a[mt][0], a[mt][1], a[mt][2], a[mt][3], b0, b1);
            }
        }
        __syncthreads();
    }

    #pragma unroll
    for (int mt = 0; mt < 4; ++mt) {
        #pragma unroll
        for (int nt = 0; nt < 4; ++nt) {
            int m = m0 + wm * 64 + mt * 16 + g;
            int n = n0 + wn * 32 + nt * 8 + 2 * t;
            float b0v = bias[n], b1v = bias[n + 1];
            float v00 = __uint_as_float(f2t((acc[mt][nt][0] + b0v) * scale));
            float v01 = __uint_as_float(f2t((acc[mt][nt][1] + b1v) * scale));
            float v10 = __uint_as_float(f2t((acc[mt][nt][2] + b0v) * scale));
            float v11 = __uint_as_float(f2t((acc[mt][nt][3] + b1v) * scale));
            *(float2*)(C + (size_t)m * Ec + n)       = make_float2(v00, v01);
            *(float2*)(C + (size_t)(m + 8) * Ec + n) = make_float2(v10, v11);
        }
    }
}

// single GEMM for output projection (fp32 out, no rounding)
__global__ __launch_bounds__(256) void gemm_tf32_o(
    const float* __restrict__ A, const float* __restrict__ W,
    const float* __restrict__ bias, float* __restrict__ C)
{
    extern __shared__ __align__(16) uint8_t smem[];
    const uint32_t sb = s2u(smem);

    const int tid  = threadIdx.x;
    const int lane = tid & 31;
    const int w    = tid >> 5;
    const int wm   = w >> 2;
    const int wn   = w & 3;
    const int g    = lane >> 2;
    const int t    = lane & 3;
    const int m0   = blockIdx.y * 128;
    const int n0   = blockIdx.x * 128;

    const char* Ab = (const char*)A + (size_t)m0 * Ec * 4;
    const char* Wb = (const char*)W + (size_t)n0 * 4;

    auto fill = [&](int s) {
        uint32_t base = sb + (uint32_t)(s & 1) * GSTG;
        #pragma unroll
        for (int q = 0; q < 4; ++q) {
            int i = q * 256 + tid;
            int r = i >> 3, c = i & 7;
            cpasync16(base + (uint32_t)(r * (APITCH * 4) + c * 16),
                      Ab + (size_t)r * (Ec * 4) + s * 128 + c * 16);
        }
        #pragma unroll
        for (int q = 0; q < 4; ++q) {
            int i = q * 256 + tid;
            int r = i >> 5, c = i & 31;
            cpasync16(base + ASTG + (uint32_t)(r * (BPITCH * 4) + c * 16),
                      Wb + (size_t)(s * 32 + r) * (Ec * 4) + c * 16);
        }
        CP_COMMIT();
    };

    float acc[4][4][4] = {};
    fill(0);

    for (int s = 0; s < 16; ++s) {
        if (s < 15) {
            fill(s + 1);
            CP_WAIT(1);
        } else {
            CP_WAIT(0);
        }
        __syncthreads();

        const uint8_t* buf = smem + (s & 1) * GSTG;
        const uint32_t* As = (const uint32_t*)buf;
        const uint32_t* Ws = (const uint32_t*)(buf + ASTG);

        #pragma unroll
        for (int k8 = 0; k8 < 4; ++k8) {
            uint32_t a[4][4];
            #pragma unroll
            for (int mt = 0; mt < 4; ++mt) {
                int m = wm * 64 + mt * 16;
                a[mt][0] = As[(m + g    ) * APITCH + k8 * 8 + t];
                a[mt][1] = As[(m + g + 8) * APITCH + k8 * 8 + t];
                a[mt][2] = As[(m + g    ) * APITCH + k8 * 8 + t + 4];
                a[mt][3] = As[(m + g + 8) * APITCH + k8 * 8 + t + 4];
            }
            #pragma unroll
            for (int nt = 0; nt < 4; ++nt) {
                uint32_t b0 = Ws[(k8 * 8 + t    ) * BPITCH + wn * 32 + nt * 8 + g];
                uint32_t b1 = Ws[(k8 * 8 + t + 4) * BPITCH + wn * 32 + nt * 8 + g];
                #pragma unroll
                for (int mt = 0; mt < 4; ++mt)
                    mma_tf32(acc[mt][nt], a[mt][0], a[mt][1], a[mt][2], a[mt][3], b0, b1);
            }
        }
        __syncthreads();
    }

    #pragma unroll
    for (int mt = 0; mt < 4; ++mt) {
        #pragma unroll
        for (int nt = 0; nt < 4; ++nt) {
            int m = m0 + wm * 64 + mt * 16 + g;
            int n = n0 + wn * 32 + nt * 8 + 2 * t;
            float b0v = bias[n], b1v = bias[n + 1];
            *(float2*)(C + (size_t)m * Ec + n) =
                make_float2(acc[mt][nt][0] + b0v, acc[mt][nt][1] + b1v);
            *(float2*)(C + (size_t)(m + 8) * Ec + n) =
                make_float2(acc[mt][nt][2] + b0v, acc[mt][nt][3] + b1v);
        }
    }
}

// ---------------------------------------------------------------------------
// Flash attention, tf32 mma. One CTA = 128 q-rows of one (b,h); 256 threads,
// 8 warps x 16 q-rows. K/V tiles (64 kv rows) loaded ONCE per 128 q-rows
// (halved smem traffic vs 64-row CTAs). Single K/V buffer; cross-CTA overlap
// (3 CTAs/SM) hides cp.async latency. Q/K/V tf32-pre-rounded by projections.
// Epilogue rounds context to tf32 for the output-projection GEMM.
// ---------------------------------------------------------------------------
#define QP 68
#define VP 72
#define QPW  (128 * QP)                      // 8704 words (Q, aliased as P)
#define KW   (64 * QP)                       // 4352 words
#define VW   (64 * VP)                       // 4608 words
#define FA_SMEM ((QPW + KW + VW + 64) * 4)   // 70912 B

__global__ __launch_bounds__(256) void flash_attn_mma(
    const float* __restrict__ Q, const float* __restrict__ K,
    const float* __restrict__ V, const int* __restrict__ mask,
    float* __restrict__ Ctx)
{
    extern __shared__ uint32_t sm[];
    uint32_t* Qs   = sm;                     // [128][QP] (aliased as Ps)
    uint32_t* Ks   = sm + QPW;               // [64][QP]
    uint32_t* Vs   = sm + QPW + KW;          // [64][VP]
    float*    mneg = (float*)(sm + QPW + KW + VW);   // [64]

    const uint32_t sbase = s2u(sm);
    const uint32_t qsb = sbase;
    const uint32_t ksb = sbase + QPW * 4;
    const uint32_t vsb = sbase + (QPW + KW) * 4;

    const int tid  = threadIdx.x;
    const int lane = tid & 31;
    const int w    = tid >> 5;      // 0..7, q-rows [w*16, w*16+16)
    const int g    = lane >> 2;
    const int t    = lane & 3;
    const int b    = blockIdx.y >> 3, h = blockIdx.y & 7;
    const int m0   = blockIdx.x * 128;
    const int w16  = w * 16;

    const char* Qb = (const char*)(Q + ((size_t)b * Sq + m0) * Ec + h * Dc);
    const char* Kb = (const char*)(K + (size_t)b * Sq * Ec + h * Dc);
    const char* Vb = (const char*)(V + (size_t)b * Sq * Ec + h * Dc);
    const int*  mb = mask + b * Sq;

    // Load Q tile 128x64 via cp.async (already tf32 bit patterns)
    #pragma unroll
    for (int p = 0; p < 8; ++p) {
        int i = p * 256 + tid;
        int r = i >> 4, c = i & 15;
        cpasync16(qsb + (uint32_t)(r * (QP * 4) + c * 16),
                  Qb + (size_t)r * (Ec * 4) + c * 16);
    }
    CP_COMMIT();
    CP_WAIT(0);
    __syncthreads();

    // Preload Q A-fragments (reused for all 32 kv tiles)
    uint32_t qf[8][4];
    #pragma unroll
    for (int k8 = 0; k8 < 8; ++k8) {
        qf[k8][0] = Qs[(w16 + g    ) * QP + k8 * 8 + t];
        qf[k8][1] = Qs[(w16 + g + 8) * QP + k8 * 8 + t];
        qf[k8][2] = Qs[(w16 + g    ) * QP + k8 * 8 + t + 4];
        qf[k8][3] = Qs[(w16 + g + 8) * QP + k8 * 8 + t + 4];
    }
    uint32_t* Ps = Qs;   // reuse buffer (each warp owns its own 16 rows)

    float o[8][4] = {};
    float mi0 = -1e30f, mi1 = -1e30f, li0 = 0.f, li1 = 0.f;

    for (int kt = 0; kt < Sq / 64; ++kt) {
        __syncthreads();   // all warps done reading Ks/Vs of prev iter
        const int n0 = kt * 64;

        // K,V tiles via cp.async: 64 rows x 16 chunks each, 256 threads
        #pragma unroll
        for (int p = 0; p < 4; ++p) {
            int i = p * 256 + tid;
            int r = i >> 4, c = i & 15;
            size_t goff = (size_t)(n0 + r) * (Ec * 4) + c * 16;
            cpasync16(ksb + (uint32_t)(r * (QP * 4) + c * 16), Kb + goff);
            cpasync16(vsb + (uint32_t)(r * (VP * 4) + c * 16), Vb + goff);
        }
        CP_COMMIT();
        if (tid < 64) mneg[tid] = (-1e9f * LOG2E) * (float)mb[n0 + tid];
        CP_WAIT(0);
        __syncthreads();

        // ---- S = Q K^T (log2e domain), 16x64 per warp ----
        float s[8][4] = {};
        #pragma unroll
        for (int k8 = 0; k8 < 8; ++k8) {
            #pragma unroll
            for (int nt = 0; nt < 8; ++nt) {
                uint32_t b0 = Ks[(nt * 8 + g) * QP + k8 * 8 + t];
                uint32_t b1 = Ks[(nt * 8 + g) * QP + k8 * 8 + t + 4];
                mma_tf32(s[nt], qf[k8][0], qf[k8][1], qf[k8][2], qf[k8][3], b0, b1);
            }
        }
        #pragma unroll
        for (int nt = 0; nt < 8; ++nt) {
            float2 mv = *(float2*)&mneg[nt * 8 + 2 * t];
            s[nt][0] += mv.x; s[nt][1] += mv.y;
            s[nt][2] += mv.x; s[nt][3] += mv.y;
        }

        // ---- online softmax (rows g and g+8; 4 threads per row) ----
        float mx0 = -1e30f, mx1 = -1e30f;
        #pragma unroll
        for (int nt = 0; nt < 8; ++nt) {
            mx0 = fmaxf(mx0, fmaxf(s[nt][0], s[nt][1]));
            mx1 = fmaxf(mx1, fmaxf(s[nt][2], s[nt][3]));
        }
        mx0 = fmaxf(mx0, __shfl_xor_sync(0xffffffffu, mx0, 1));
        mx0 = fmaxf(mx0, __shfl_xor_sync(0xffffffffu, mx0, 2));
        mx1 = fmaxf(mx1, __shfl_xor_sync(0xffffffffu, mx1, 1));
        mx1 = fmaxf(mx1, __shfl_xor_sync(0xffffffffu, mx1, 2));

        float mn0 = fmaxf(mi0, mx0), mn1 = fmaxf(mi1, mx1);
        float al0 = exp2f(mi0 - mn0), al1 = exp2f(mi1 - mn1);
        float sum0 = 0.f, sum1 = 0.f;
        #pragma unroll
        for (int nt = 0; nt < 8; ++nt) {
            s[nt][0] = exp2f(s[nt][0] - mn0);
            s[nt][1] = exp2f(s[nt][1] - mn0);
            s[nt][2] = exp2f(s[nt][2] - mn1);
            s[nt][3] = exp2f(s[nt][3] - mn1);
            sum0 += s[nt][0] + s[nt][1];
            sum1 += s[nt][2] + s[nt][3];
        }
        sum0 += __shfl_xor_sync(0xffffffffu, sum0, 1);
        sum0 += __shfl_xor_sync(0xffffffffu, sum0, 2);
        sum1 += __shfl_xor_sync(0xffffffffu, sum1, 1);
        sum1 += __shfl_xor_sync(0xffffffffu, sum1, 2);
        li0 = li0 * al0 + sum0;  mi0 = mn0;
        li1 = li1 * al1 + sum1;  mi1 = mn1;
        #pragma unroll
        for (int dt = 0; dt < 8; ++dt) {
            o[dt][0] *= al0; o[dt][1] *= al0;
            o[dt][2] *= al1; o[dt][3] *= al1;
        }

        // ---- store P (tf32) into Ps; each warp owns its own 16 rows ----
        #pragma unroll
        for (int nt = 0; nt < 8; ++nt) {
            *(uint2*)&Ps[(w16 + g    ) * QP + nt * 8 + 2 * t] =
                make_uint2(f2t(s[nt][0]), f2t(s[nt][1]));
            *(uint2*)&Ps[(w16 + g + 8) * QP + nt * 8 + 2 * t] =
                make_uint2(f2t(s[nt][2]), f2t(s[nt][3]));
        }
        __syncwarp();

        // ---- O += P @ V ----
        #pragma unroll
        for (int k8 = 0; k8 < 8; ++k8) {
            uint32_t a0 = Ps[(w16 + g    ) * QP + k8 * 8 + t];
            uint32_t a1 = Ps[(w16 + g + 8) * QP + k8 * 8 + t];
            uint32_t a2 = Ps[(w16 + g    ) * QP + k8 * 8 + t + 4];
            uint32_t a3 = Ps[(w16 + g + 8) * QP + k8 * 8 + t + 4];
            #pragma unroll
            for (int dt = 0; dt < 8; ++dt) {
                uint32_t b0 = Vs[(k8 * 8 + t    ) * VP + dt * 8 + g];
                uint32_t b1 = Vs[(k8 * 8 + t + 4) * VP + dt * 8 + g];
                mma_tf32(o[dt], a0, a1, a2, a3, b0, b1);
            }
        }
    }

    // Epilogue: normalize, round to tf32 (feeds output-proj GEMM), write
    float inv0 = 1.f / li0, inv1 = 1.f / li1;
    float* Cb = Ctx + ((size_t)b * Sq + m0 + w16) * Ec + h * Dc;
    #pragma unroll
    for (int dt = 0; dt < 8; ++dt) {
        int n = dt * 8 + 2 * t;
        *(uint2*)(Cb + (size_t)g * Ec + n) =
            make_uint2(f2t(o[dt][0] * inv0), f2t(o[dt][1] * inv0));
        *(uint2*)(Cb + (size_t)(g + 8) * Ec + n) =
            make_uint2(f2t(o[dt][2] * inv1), f2t(o[dt][3] * inv1));
    }
}

// ---------------------------------------------------------------------------
// Host launcher
// ---------------------------------------------------------------------------
extern "C" void kernel_launch(void* const* d_in, const int* in_sizes, int n_in,
                              void* d_out, int out_size)
{
    const float* value = (const float*)d_in[0];
    const float* key   = (const float*)d_in[1];
    const float* query = (const float*)d_in[2];
    const int*   mask  = (const int*)d_in[3];
    const float* wq = (const float*)d_in[4];
    const float* bq = (const float*)d_in[5];
    const float* wk = (const float*)d_in[6];
    const float* bk = (const float*)d_in[7];
    const float* wv = (const float*)d_in[8];
    const float* bv = (const float*)d_in[9];
    const float* wo = (const float*)d_in[10];
    const float* bo = (const float*)d_in[11];
    float* out = (float*)d_out;

    float *Qp, *Kp, *Vp, *Cp, *T3p, *WT4p;
    cudaGetSymbolAddress((void**)&Qp, g_Q);
    cudaGetSymbolAddress((void**)&Kp, g_K);
    cudaGetSymbolAddress((void**)&Vp, g_V);
    cudaGetSymbolAddress((void**)&Cp, g_C);
    cudaGetSymbolAddress((void**)&T3p, g_T3);
    cudaGetSymbolAddress((void**)&WT4p, g_WT4);

    cudaFuncSetAttribute(flash_attn_mma, cudaFuncAttributeMaxDynamicSharedMemorySize,
                         FA_SMEM);
    cudaFuncSetAttribute(gemm_tf32_qkv, cudaFuncAttributeMaxDynamicSharedMemorySize,
                         GSMEM);
    cudaFuncSetAttribute(gemm_tf32_o, cudaFuncAttributeMaxDynamicSharedMemorySize,
                         GSMEM);

    const int n4A = Mrows * Ec / 4;     // 2,097,152
    const int n4W = Ec * Ec / 4;        // 65,536

    // tf32-round all operands (z order matches gemm: q, k, v)
    conv3<<<3 * n4A / 256, 256>>>(query, key, value, T3p, n4A);
    convW4<<<4 * n4W / 256, 256>>>(wq, wk, wv, wo, WT4p, n4W);

    // batched Q/K/V projections (Q folds 0.125*log2e; outputs tf32-rounded)
    gemm_tf32_qkv<<<dim3(Ec / 128, Mrows / 128, 3), 256, GSMEM>>>(
        T3p, WT4p, bq, bk, bv, Qp, Kp, Vp);

    // attention: 128 q-rows per CTA, grid (16, 64)
    flash_attn_mma<<<dim3(Sq / 128, Bc * Hc), 256, FA_SMEM>>>(Qp, Kp, Vp, mask, Cp);

    // output projection (fp32 output)
    gemm_tf32_o<<<dim3(Ec / 128, Mrows / 128), 256, GSMEM>>>(
        Cp, WT4p + (size_t)3 * Ec * Ec, bo, out);
}

// round 15
// speedup vs baseline: 1.5597x; 1.5597x over previous
#include <cuda_runtime.h>
#include <cuda_bf16.h>
#include <cstdint>

// Problem constants
#define Bc 8
#define Sq 2048
#define Ec 512
#define Hc 8
#define Dc 64
#define Mrows (Bc * Sq)   // 16384

#define LOG2E 1.4426950408889634f

// Scratch (no cudaMalloc allowed)
__device__ float g_Q[(size_t)Mrows * Ec];
__device__ float g_K[(size_t)Mrows * Ec];
__device__ float g_V[(size_t)Mrows * Ec];
__device__ float g_C[(size_t)Mrows * Ec];
__device__ float g_T3[(size_t)3 * Mrows * Ec];   // tf32-rounded q/k/v inputs
__device__ float g_WT4[(size_t)4 * Ec * Ec];     // tf32-rounded wq/wk/wv/wo

// ---------------------------------------------------------------------------
// helpers
// ---------------------------------------------------------------------------
__device__ __forceinline__ uint32_t f2t(float x) {
    uint32_t u;
    asm("cvt.rna.tf32.f32 %0, %1;" : "=r"(u) : "f"(x));
    return u;
}

__device__ __forceinline__ void mma_tf32(float c[4],
    uint32_t a0, uint32_t a1, uint32_t a2, uint32_t a3,
    uint32_t b0, uint32_t b1)
{
    asm volatile(
        "mma.sync.aligned.m16n8k8.row.col.f32.tf32.tf32.f32 "
        "{%0,%1,%2,%3}, {%4,%5,%6,%7}, {%8,%9}, {%0,%1,%2,%3};"
        : "+f"(c[0]), "+f"(c[1]), "+f"(c[2]), "+f"(c[3])
        : "r"(a0), "r"(a1), "r"(a2), "r"(a3), "r"(b0), "r"(b1));
}

__device__ __forceinline__ uint32_t s2u(const void* p) {
    uint32_t a;
    asm("{ .reg .u64 t; cvta.to.shared.u64 t, %1; cvt.u32.u64 %0, t; }"
        : "=r"(a) : "l"(p));
    return a;
}

__device__ __forceinline__ void cpasync16(uint32_t dst, const void* src) {
    asm volatile("cp.async.cg.shared.global [%0], [%1], 16;" :: "r"(dst), "l"(src));
}
#define CP_COMMIT() asm volatile("cp.async.commit_group;" ::: "memory")
#define CP_WAIT(n)  asm volatile("cp.async.wait_group %0;" :: "n"(n) : "memory")

// ---------------------------------------------------------------------------
// merged tf32 rounding: 3 activation inputs -> g_T3
// ---------------------------------------------------------------------------
__global__ __launch_bounds__(256) void conv3(
    const float* __restrict__ a0, const float* __restrict__ a1,
    const float* __restrict__ a2, float* __restrict__ y, int n4)
{
    int i = blockIdx.x * 256 + threadIdx.x;
    if (i >= 3 * n4) return;
    int which = i / n4;
    int j = i - which * n4;
    const float* src = which == 0 ? a0 : (which == 1 ? a1 : a2);
    float4 v = ((const float4*)src)[j];
    ((uint4*)y)[i] = make_uint4(f2t(v.x), f2t(v.y), f2t(v.z), f2t(v.w));
}

// merged tf32 rounding: 4 weight matrices -> g_WT4
__global__ __launch_bounds__(256) void convW4(
    const float* __restrict__ w0, const float* __restrict__ w1,
    const float* __restrict__ w2, const float* __restrict__ w3,
    float* __restrict__ y, int n4)
{
    int i = blockIdx.x * 256 + threadIdx.x;
    if (i >= 4 * n4) return;
    int which = i / n4;
    int j = i - which * n4;
    const float* src = which == 0 ? w0 : (which == 1 ? w1 : (which == 2 ? w2 : w3));
    float4 v = ((const float4*)src)[j];
    ((uint4*)y)[i] = make_uint4(f2t(v.x), f2t(v.y), f2t(v.z), f2t(v.w));
}

// ---------------------------------------------------------------------------
// tf32 GEMM: C = round_tf32((A @ W + bias) * scale)
// Batched over gridDim.z = 3 (Q/K/V projections) or single (output proj).
// CTA tile 128x128, Bk=32, double-buffered cp.async.
// 8 warps = 2(m) x 4(n); warp tile 64x32 = 4 m16 x 4 n8.
// ---------------------------------------------------------------------------
#define APITCH 36
#define BPITCH 136
#define ASTG (128 * APITCH * 4)     // 18432 B
#define BSTG (32 * BPITCH * 4)      // 17408 B
#define GSTG (ASTG + BSTG)          // 35840 B
#define GSMEM (2 * GSTG)            // 71680 B

__global__ __launch_bounds__(256) void gemm_tf32_qkv(
    const float* __restrict__ A3, const float* __restrict__ W4,
    const float* __restrict__ bq, const float* __restrict__ bk,
    const float* __restrict__ bv,
    float* __restrict__ Qo, float* __restrict__ Ko, float* __restrict__ Vo)
{
    extern __shared__ __align__(16) uint8_t smem[];
    const uint32_t sb = s2u(smem);

    const int tid  = threadIdx.x;
    const int lane = tid & 31;
    const int w    = tid >> 5;
    const int wm   = w >> 2;
    const int wn   = w & 3;
    const int g    = lane >> 2;
    const int t    = lane & 3;
    const int m0   = blockIdx.y * 128;
    const int n0   = blockIdx.x * 128;
    const int z    = blockIdx.z;

    const float* bias = z == 0 ? bq : (z == 1 ? bk : bv);
    float* C          = z == 0 ? Qo : (z == 1 ? Ko : Vo);
    const float scale = z == 0 ? 0.125f * LOG2E : 1.0f;

    const char* Ab = (const char*)(A3 + (size_t)z * Mrows * Ec) + (size_t)m0 * Ec * 4;
    const char* Wb = (const char*)(W4 + (size_t)z * Ec * Ec) + (size_t)n0 * 4;

    auto fill = [&](int s) {
        uint32_t base = sb + (uint32_t)(s & 1) * GSTG;
        #pragma unroll
        for (int q = 0; q < 4; ++q) {
            int i = q * 256 + tid;
            int r = i >> 3, c = i & 7;
            cpasync16(base + (uint32_t)(r * (APITCH * 4) + c * 16),
                      Ab + (size_t)r * (Ec * 4) + s * 128 + c * 16);
        }
        #pragma unroll
        for (int q = 0; q < 4; ++q) {
            int i = q * 256 + tid;
            int r = i >> 5, c = i & 31;
            cpasync16(base + ASTG + (uint32_t)(r * (BPITCH * 4) + c * 16),
                      Wb + (size_t)(s * 32 + r) * (Ec * 4) + c * 16);
        }
        CP_COMMIT();
    };

    float acc[4][4][4] = {};
    fill(0);

    for (int s = 0; s < 16; ++s) {
        if (s < 15) {
            fill(s + 1);
            CP_WAIT(1);
        } else {
            CP_WAIT(0);
        }
        __syncthreads();

        const uint8_t* buf = smem + (s & 1) * GSTG;
        const uint32_t* As = (const uint32_t*)buf;
        const uint32_t* Ws = (const uint32_t*)(buf + ASTG);

        #pragma unroll
        for (int k8 = 0; k8 < 4; ++k8) {
            uint32_t a[4][4];
            #pragma unroll
            for (int mt = 0; mt < 4; ++mt) {
                int m = wm * 64 + mt * 16;
                a[mt][0] = As[(m + g    ) * APITCH + k8 * 8 + t];
                a[mt][1] = As[(m + g + 8) * APITCH + k8 * 8 + t];
                a[mt][2] = As[(m + g    ) * APITCH + k8 * 8 + t + 4];
                a[mt][3] = As[(m + g + 8) * APITCH + k8 * 8 + t + 4];
            }
            #pragma unroll
            for (int nt = 0; nt < 4; ++nt) {
                uint32_t b0 = Ws[(k8 * 8 + t    ) * BPITCH + wn * 32 + nt * 8 + g];
                uint32_t b1 = Ws[(k8 * 8 + t + 4) * BPITCH + wn * 32 + nt * 8 + g];
                #pragma unroll
                for (int mt = 0; mt < 4; ++mt)
                    mma_tf32(acc[mt][nt], a[mt][0], a[mt][1], a[mt][2], a[mt][3], b0, b1);
            }
        }
        __syncthreads();
    }

    #pragma unroll
    for (int mt = 0; mt < 4; ++mt) {
        #pragma unroll
        for (int nt = 0; nt < 4; ++nt) {
            int m = m0 + wm * 64 + mt * 16 + g;
            int n = n0 + wn * 32 + nt * 8 + 2 * t;
            float b0v = bias[n], b1v = bias[n + 1];
            float v00 = __uint_as_float(f2t((acc[mt][nt][0] + b0v) * scale));
            float v01 = __uint_as_float(f2t((acc[mt][nt][1] + b1v) * scale));
            float v10 = __uint_as_float(f2t((acc[mt][nt][2] + b0v) * scale));
            float v11 = __uint_as_float(f2t((acc[mt][nt][3] + b1v) * scale));
            *(float2*)(C + (size_t)m * Ec + n)       = make_float2(v00, v01);
            *(float2*)(C + (size_t)(m + 8) * Ec + n) = make_float2(v10, v11);
        }
    }
}

// single GEMM for output projection (fp32 out, no rounding)
__global__ __launch_bounds__(256) void gemm_tf32_o(
    const float* __restrict__ A, const float* __restrict__ W,
    const float* __restrict__ bias, float* __restrict__ C)
{
    extern __shared__ __align__(16) uint8_t smem[];
    const uint32_t sb = s2u(smem);

    const int tid  = threadIdx.x;
    const int lane = tid & 31;
    const int w    = tid >> 5;
    const int wm   = w >> 2;
    const int wn   = w & 3;
    const int g    = lane >> 2;
    const int t    = lane & 3;
    const int m0   = blockIdx.y * 128;
    const int n0   = blockIdx.x * 128;

    const char* Ab = (const char*)A + (size_t)m0 * Ec * 4;
    const char* Wb = (const char*)W + (size_t)n0 * 4;

    auto fill = [&](int s) {
        uint32_t base = sb + (uint32_t)(s & 1) * GSTG;
        #pragma unroll
        for (int q = 0; q < 4; ++q) {
            int i = q * 256 + tid;
            int r = i >> 3, c = i & 7;
            cpasync16(base + (uint32_t)(r * (APITCH * 4) + c * 16),
                      Ab + (size_t)r * (Ec * 4) + s * 128 + c * 16);
        }
        #pragma unroll
        for (int q = 0; q < 4; ++q) {
            int i = q * 256 + tid;
            int r = i >> 5, c = i & 31;
            cpasync16(base + ASTG + (uint32_t)(r * (BPITCH * 4) + c * 16),
                      Wb + (size_t)(s * 32 + r) * (Ec * 4) + c * 16);
        }
        CP_COMMIT();
    };

    float acc[4][4][4] = {};
    fill(0);

    for (int s = 0; s < 16; ++s) {
        if (s < 15) {
            fill(s + 1);
            CP_WAIT(1);
        } else {
            CP_WAIT(0);
        }
        __syncthreads();

        const uint8_t* buf = smem + (s & 1) * GSTG;
        const uint32_t* As = (const uint32_t*)buf;
        const uint32_t* Ws = (const uint32_t*)(buf + ASTG);

        #pragma unroll
        for (int k8 = 0; k8 < 4; ++k8) {
            uint32_t a[4][4];
            #pragma unroll
            for (int mt = 0; mt < 4; ++mt) {
                int m = wm * 64 + mt * 16;
                a[mt][0] = As[(m + g    ) * APITCH + k8 * 8 + t];
                a[mt][1] = As[(m + g + 8) * APITCH + k8 * 8 + t];
                a[mt][2] = As[(m + g    ) * APITCH + k8 * 8 + t + 4];
                a[mt][3] = As[(m + g + 8) * APITCH + k8 * 8 + t + 4];
            }
            #pragma unroll
            for (int nt = 0; nt < 4; ++nt) {
                uint32_t b0 = Ws[(k8 * 8 + t    ) * BPITCH + wn * 32 + nt * 8 + g];
                uint32_t b1 = Ws[(k8 * 8 + t + 4) * BPITCH + wn * 32 + nt * 8 + g];
                #pragma unroll
                for (int mt = 0; mt < 4; ++mt)
                    mma_tf32(acc[mt][nt], a[mt][0], a[mt][1], a[mt][2], a[mt][3], b0, b1);
            }
        }
        __syncthreads();
    }

    #pragma unroll
    for (int mt = 0; mt < 4; ++mt) {
        #pragma unroll
        for (int nt = 0; nt < 4; ++nt) {
            int m = m0 + wm * 64 + mt * 16 + g;
            int n = n0 + wn * 32 + nt * 8 + 2 * t;
            float b0v = bias[n], b1v = bias[n + 1];
            *(float2*)(C + (size_t)m * Ec + n) =
                make_float2(acc[mt][nt][0] + b0v, acc[mt][nt][1] + b1v);
            *(float2*)(C + (size_t)(m + 8) * Ec + n) =
                make_float2(acc[mt][nt][2] + b0v, acc[mt][nt][3] + b1v);
        }
    }
}

// ---------------------------------------------------------------------------
// Flash attention, tf32 mma — round-11 structure (64 q-rows/CTA, 128 threads,
// single K/V buffer, cross-CTA latency hiding) + __launch_bounds__(128,4) to
// cap regs at 128 and get 4 CTAs/SM (smem 4 x 53.5KB = 214KB fits carveout).
// Q/K/V tf32-pre-rounded by projections. Epilogue rounds context to tf32.
// ---------------------------------------------------------------------------
#define QP 68
#define VP 72
#define FA_SMEM ((2 * 64 * QP + 64 * VP + 64) * 4)   // 53504 B

__global__ __launch_bounds__(128, 4) void flash_attn_mma(
    const float* __restrict__ Q, const float* __restrict__ K,
    const float* __restrict__ V, const int* __restrict__ mask,
    float* __restrict__ Ctx)
{
    extern __shared__ uint32_t sm[];
    uint32_t* Qs = sm;                       // [64][QP]  (also Ps after preload)
    uint32_t* Ks = sm + 64 * QP;             // [64][QP]
    uint32_t* Vs = sm + 2 * 64 * QP;         // [64][VP]
    float* mneg  = (float*)(sm + 2 * 64 * QP + 64 * VP);  // [64]

    const uint32_t sbase = s2u(sm);
    const uint32_t qsb = sbase;
    const uint32_t ksb = sbase + 64 * QP * 4;
    const uint32_t vsb = sbase + 2 * 64 * QP * 4;

    const int tid  = threadIdx.x;
    const int lane = tid & 31;
    const int w    = tid >> 5;
    const int g    = lane >> 2;
    const int t    = lane & 3;
    const int b    = blockIdx.y >> 3, h = blockIdx.y & 7;
    const int m0   = blockIdx.x * 64;
    const int w16  = w * 16;

    const char* Qb = (const char*)(Q + ((size_t)b * Sq + m0) * Ec + h * Dc);
    const char* Kb = (const char*)(K + (size_t)b * Sq * Ec + h * Dc);
    const char* Vb = (const char*)(V + (size_t)b * Sq * Ec + h * Dc);
    const int*  mb = mask + b * Sq;

    // Load Q tile 64x64 via cp.async (already tf32 bit patterns)
    #pragma unroll
    for (int p = 0; p < 8; ++p) {
        int i = p * 128 + tid;
        int r = i >> 4, c = i & 15;
        cpasync16(qsb + (uint32_t)(r * (QP * 4) + c * 16),
                  Qb + (size_t)r * (Ec * 4) + c * 16);
    }
    CP_COMMIT();
    CP_WAIT(0);
    __syncthreads();

    // Preload Q A-fragments into registers (reused for all 32 kv tiles)
    uint32_t qf[8][4];
    #pragma unroll
    for (int k8 = 0; k8 < 8; ++k8) {
        qf[k8][0] = Qs[(w16 + g    ) * QP + k8 * 8 + t];
        qf[k8][1] = Qs[(w16 + g + 8) * QP + k8 * 8 + t];
        qf[k8][2] = Qs[(w16 + g    ) * QP + k8 * 8 + t + 4];
        qf[k8][3] = Qs[(w16 + g + 8) * QP + k8 * 8 + t + 4];
    }
    uint32_t* Ps = Qs;   // reuse buffer

    float o[8][4] = {};
    float mi0 = -1e30f, mi1 = -1e30f, li0 = 0.f, li1 = 0.f;

    for (int kt = 0; kt < Sq / 64; ++kt) {
        __syncthreads();   // all warps done reading Ks/Vs/Ps of prev iter
        const int n0 = kt * 64;

        // K,V tiles via cp.async (no cvt, no register round-trip)
        #pragma unroll
        for (int p = 0; p < 8; ++p) {
            int i = p * 128 + tid;
            int r = i >> 4, c = i & 15;
            size_t goff = (size_t)(n0 + r) * (Ec * 4) + c * 16;
            cpasync16(ksb + (uint32_t)(r * (QP * 4) + c * 16), Kb + goff);
            cpasync16(vsb + (uint32_t)(r * (VP * 4) + c * 16), Vb + goff);
        }
        CP_COMMIT();
        CP_WAIT(0);
        if (tid < 64) mneg[tid] = (-1e9f * LOG2E) * (float)mb[n0 + tid];
        __syncthreads();

        // ---- S = Q K^T (log2e domain), 16x64 per warp ----
        float s[8][4] = {};
        #pragma unroll
        for (int k8 = 0; k8 < 8; ++k8) {
            #pragma unroll
            for (int nt = 0; nt < 8; ++nt) {
                uint32_t b0 = Ks[(nt * 8 + g) * QP + k8 * 8 + t];
                uint32_t b1 = Ks[(nt * 8 + g) * QP + k8 * 8 + t + 4];
                mma_tf32(s[nt], qf[k8][0], qf[k8][1], qf[k8][2], qf[k8][3], b0, b1);
            }
        }
        #pragma unroll
        for (int nt = 0; nt < 8; ++nt) {
            float2 mv = *(float2*)&mneg[nt * 8 + 2 * t];
            s[nt][0] += mv.x; s[nt][1] += mv.y;
            s[nt][2] += mv.x; s[nt][3] += mv.y;
        }

        // ---- online softmax (rows g and g+8; 4 threads per row) ----
        float mx0 = -1e30f, mx1 = -1e30f;
        #pragma unroll
        for (int nt = 0; nt < 8; ++nt) {
            mx0 = fmaxf(mx0, fmaxf(s[nt][0], s[nt][1]));
            mx1 = fmaxf(mx1, fmaxf(s[nt][2], s[nt][3]));
        }
        mx0 = fmaxf(mx0, __shfl_xor_sync(0xffffffffu, mx0, 1));
        mx0 = fmaxf(mx0, __shfl_xor_sync(0xffffffffu, mx0, 2));
        mx1 = fmaxf(mx1, __shfl_xor_sync(0xffffffffu, mx1, 1));
        mx1 = fmaxf(mx1, __shfl_xor_sync(0xffffffffu, mx1, 2));

        float mn0 = fmaxf(mi0, mx0), mn1 = fmaxf(mi1, mx1);
        float al0 = exp2f(mi0 - mn0), al1 = exp2f(mi1 - mn1);
        float sum0 = 0.f, sum1 = 0.f;
        #pragma unroll
        for (int nt = 0; nt < 8; ++nt) {
            s[nt][0] = exp2f(s[nt][0] - mn0);
            s[nt][1] = exp2f(s[nt][1] - mn0);
            s[nt][2] = exp2f(s[nt][2] - mn1);
            s[nt][3] = exp2f(s[nt][3] - mn1);
            sum0 += s[nt][0] + s[nt][1];
            sum1 += s[nt][2] + s[nt][3];
        }
        sum0 += __shfl_xor_sync(0xffffffffu, sum0, 1);
        sum0 += __shfl_xor_sync(0xffffffffu, sum0, 2);
        sum1 += __shfl_xor_sync(0xffffffffu, sum1, 1);
        sum1 += __shfl_xor_sync(0xffffffffu, sum1, 2);
        li0 = li0 * al0 + sum0;  mi0 = mn0;
        li1 = li1 * al1 + sum1;  mi1 = mn1;
        #pragma unroll
        for (int dt = 0; dt < 8; ++dt) {
            o[dt][0] *= al0; o[dt][1] *= al0;
            o[dt][2] *= al1; o[dt][3] *= al1;
        }

        // ---- store P (tf32) into Ps; each warp owns its own 16 rows ----
        #pragma unroll
        for (int nt = 0; nt < 8; ++nt) {
            *(uint2*)&Ps[(w16 + g    ) * QP + nt * 8 + 2 * t] =
                make_uint2(f2t(s[nt][0]), f2t(s[nt][1]));
            *(uint2*)&Ps[(w16 + g + 8) * QP + nt * 8 + 2 * t] =
                make_uint2(f2t(s[nt][2]), f2t(s[nt][3]));
        }
        __syncwarp();

        // ---- O += P @ V ----
        #pragma unroll
        for (int k8 = 0; k8 < 8; ++k8) {
            uint32_t a0 = Ps[(w16 + g    ) * QP + k8 * 8 + t];
            uint32_t a1 = Ps[(w16 + g + 8) * QP + k8 * 8 + t];
            uint32_t a2 = Ps[(w16 + g    ) * QP + k8 * 8 + t + 4];
            uint32_t a3 = Ps[(w16 + g + 8) * QP + k8 * 8 + t + 4];
            #pragma unroll
            for (int dt = 0; dt < 8; ++dt) {
                uint32_t b0 = Vs[(k8 * 8 + t    ) * VP + dt * 8 + g];
                uint32_t b1 = Vs[(k8 * 8 + t + 4) * VP + dt * 8 + g];
                mma_tf32(o[dt], a0, a1, a2, a3, b0, b1);
            }
        }
    }

    // Epilogue: normalize, round to tf32 (feeds output-proj GEMM), write
    float inv0 = 1.f / li0, inv1 = 1.f / li1;
    float* Cb = Ctx + ((size_t)b * Sq + m0 + w16) * Ec + h * Dc;
    #pragma unroll
    for (int dt = 0; dt < 8; ++dt) {
        int n = dt * 8 + 2 * t;
        *(uint2*)(Cb + (size_t)g * Ec + n) =
            make_uint2(f2t(o[dt][0] * inv0), f2t(o[dt][1] * inv0));
        *(uint2*)(Cb + (size_t)(g + 8) * Ec + n) =
            make_uint2(f2t(o[dt][2] * inv1), f2t(o[dt][3] * inv1));
    }
}

// ---------------------------------------------------------------------------
// Host launcher
// ---------------------------------------------------------------------------
extern "C" void kernel_launch(void* const* d_in, const int* in_sizes, int n_in,
                              void* d_out, int out_size)
{
    const float* value = (const float*)d_in[0];
    const float* key   = (const float*)d_in[1];
    const float* query = (const float*)d_in[2];
    const int*   mask  = (const int*)d_in[3];
    const float* wq = (const float*)d_in[4];
    const float* bq = (const float*)d_in[5];
    const float* wk = (const float*)d_in[6];
    const float* bk = (const float*)d_in[7];
    const float* wv = (const float*)d_in[8];
    const float* bv = (const float*)d_in[9];
    const float* wo = (const float*)d_in[10];
    const float* bo = (const float*)d_in[11];
    float* out = (float*)d_out;

    float *Qp, *Kp, *Vp, *Cp, *T3p, *WT4p;
    cudaGetSymbolAddress((void**)&Qp, g_Q);
    cudaGetSymbolAddress((void**)&Kp, g_K);
    cudaGetSymbolAddress((void**)&Vp, g_V);
    cudaGetSymbolAddress((void**)&Cp, g_C);
    cudaGetSymbolAddress((void**)&T3p, g_T3);
    cudaGetSymbolAddress((void**)&WT4p, g_WT4);

    cudaFuncSetAttribute(flash_attn_mma, cudaFuncAttributeMaxDynamicSharedMemorySize,
                         FA_SMEM);
    cudaFuncSetAttribute(gemm_tf32_qkv, cudaFuncAttributeMaxDynamicSharedMemorySize,
                         GSMEM);
    cudaFuncSetAttribute(gemm_tf32_o, cudaFuncAttributeMaxDynamicSharedMemorySize,
                         GSMEM);

    const int n4A = Mrows * Ec / 4;     // 2,097,152
    const int n4W = Ec * Ec / 4;        // 65,536

    // tf32-round all operands (z order matches gemm: q, k, v)
    conv3<<<3 * n4A / 256, 256>>>(query, key, value, T3p, n4A);
    convW4<<<4 * n4W / 256, 256>>>(wq, wk, wv, wo, WT4p, n4W);

    // batched Q/K/V projections (Q folds 0.125*log2e; outputs tf32-rounded)
    gemm_tf32_qkv<<<dim3(Ec / 128, Mrows / 128, 3), 256, GSMEM>>>(
        T3p, WT4p, bq, bk, bv, Qp, Kp, Vp);

    // attention: 64 q-rows per CTA, grid (32, 64)
    flash_attn_mma<<<dim3(Sq / 64, Bc * Hc), 128, FA_SMEM>>>(Qp, Kp, Vp, mask, Cp);

    // output projection (fp32 output)
    gemm_tf32_o<<<dim3(Ec / 128, Mrows / 128), 256, GSMEM>>>(
        Cp, WT4p + (size_t)3 * Ec * Ec, bo, out);
}

// round 16
// speedup vs baseline: 1.7560x; 1.1259x over previous
#include <cuda_runtime.h>
#include <cuda_bf16.h>
#include <cstdint>

// Problem constants
#define Bc 8
#define Sq 2048
#define Ec 512
#define Hc 8
#define Dc 64
#define Mrows (Bc * Sq)   // 16384

#define LOG2E 1.4426950408889634f

// Scratch (no cudaMalloc allowed)
__device__ float g_Q[(size_t)Mrows * Ec];
__device__ float g_K[(size_t)Mrows * Ec];
__device__ float g_V[(size_t)Mrows * Ec];
__device__ float g_C[(size_t)Mrows * Ec];
__device__ float g_T3[(size_t)3 * Mrows * Ec];   // tf32-rounded q/k/v inputs
__device__ float g_WT4[(size_t)4 * Ec * Ec];     // tf32-rounded wq/wk/wv/wo

// ---------------------------------------------------------------------------
// helpers
// ---------------------------------------------------------------------------
__device__ __forceinline__ uint32_t f2t(float x) {
    uint32_t u;
    asm("cvt.rna.tf32.f32 %0, %1;" : "=r"(u) : "f"(x));
    return u;
}

__device__ __forceinline__ float ex2(float x) {
    float y;
    asm("ex2.approx.ftz.f32 %0, %1;" : "=f"(y) : "f"(x));
    return y;
}

__device__ __forceinline__ void mma_tf32(float c[4],
    uint32_t a0, uint32_t a1, uint32_t a2, uint32_t a3,
    uint32_t b0, uint32_t b1)
{
    asm volatile(
        "mma.sync.aligned.m16n8k8.row.col.f32.tf32.tf32.f32 "
        "{%0,%1,%2,%3}, {%4,%5,%6,%7}, {%8,%9}, {%0,%1,%2,%3};"
        : "+f"(c[0]), "+f"(c[1]), "+f"(c[2]), "+f"(c[3])
        : "r"(a0), "r"(a1), "r"(a2), "r"(a3), "r"(b0), "r"(b1));
}

__device__ __forceinline__ uint32_t s2u(const void* p) {
    uint32_t a;
    asm("{ .reg .u64 t; cvta.to.shared.u64 t, %1; cvt.u32.u64 %0, t; }"
        : "=r"(a) : "l"(p));
    return a;
}

__device__ __forceinline__ void cpasync16(uint32_t dst, const void* src) {
    asm volatile("cp.async.cg.shared.global [%0], [%1], 16;" :: "r"(dst), "l"(src));
}
#define CP_COMMIT() asm volatile("cp.async.commit_group;" ::: "memory")
#define CP_WAIT(n)  asm volatile("cp.async.wait_group %0;" :: "n"(n) : "memory")

// ---------------------------------------------------------------------------
// merged tf32 rounding: 3 activation inputs -> g_T3
// ---------------------------------------------------------------------------
__global__ __launch_bounds__(256) void conv3(
    const float* __restrict__ a0, const float* __restrict__ a1,
    const float* __restrict__ a2, float* __restrict__ y, int n4)
{
    int i = blockIdx.x * 256 + threadIdx.x;
    if (i >= 3 * n4) return;
    int which = i / n4;
    int j = i - which * n4;
    const float* src = which == 0 ? a0 : (which == 1 ? a1 : a2);
    float4 v = ((const float4*)src)[j];
    ((uint4*)y)[i] = make_uint4(f2t(v.x), f2t(v.y), f2t(v.z), f2t(v.w));
}

// merged tf32 rounding: 4 weight matrices -> g_WT4
__global__ __launch_bounds__(256) void convW4(
    const float* __restrict__ w0, const float* __restrict__ w1,
    const float* __restrict__ w2, const float* __restrict__ w3,
    float* __restrict__ y, int n4)
{
    int i = blockIdx.x * 256 + threadIdx.x;
    if (i >= 4 * n4) return;
    int which = i / n4;
    int j = i - which * n4;
    const float* src = which == 0 ? w0 : (which == 1 ? w1 : (which == 2 ? w2 : w3));
    float4 v = ((const float4*)src)[j];
    ((uint4*)y)[i] = make_uint4(f2t(v.x), f2t(v.y), f2t(v.z), f2t(v.w));
}

// ---------------------------------------------------------------------------
// tf32 GEMM: C = round_tf32((A @ W + bias) * scale)
// Batched over gridDim.z = 3 (Q/K/V projections) or single (output proj).
// CTA tile 128x128, Bk=32, double-buffered cp.async.
// 8 warps = 2(m) x 4(n); warp tile 64x32 = 4 m16 x 4 n8.
// ---------------------------------------------------------------------------
#define APITCH 36
#define BPITCH 136
#define ASTG (128 * APITCH * 4)     // 18432 B
#define BSTG (32 * BPITCH * 4)      // 17408 B
#define GSTG (ASTG + BSTG)          // 35840 B
#define GSMEM (2 * GSTG)            // 71680 B

__global__ __launch_bounds__(256) void gemm_tf32_qkv(
    const float* __restrict__ A3, const float* __restrict__ W4,
    const float* __restrict__ bq, const float* __restrict__ bk,
    const float* __restrict__ bv,
    float* __restrict__ Qo, float* __restrict__ Ko, float* __restrict__ Vo)
{
    extern __shared__ __align__(16) uint8_t smem[];
    const uint32_t sb = s2u(smem);

    const int tid  = threadIdx.x;
    const int lane = tid & 31;
    const int w    = tid >> 5;
    const int wm   = w >> 2;
    const int wn   = w & 3;
    const int g    = lane >> 2;
    const int t    = lane & 3;
    const int m0   = blockIdx.y * 128;
    const int n0   = blockIdx.x * 128;
    const int z    = blockIdx.z;

    const float* bias = z == 0 ? bq : (z == 1 ? bk : bv);
    float* C          = z == 0 ? Qo : (z == 1 ? Ko : Vo);
    const float scale = z == 0 ? 0.125f * LOG2E : 1.0f;

    const char* Ab = (const char*)(A3 + (size_t)z * Mrows * Ec) + (size_t)m0 * Ec * 4;
    const char* Wb = (const char*)(W4 + (size_t)z * Ec * Ec) + (size_t)n0 * 4;

    auto fill = [&](int s) {
        uint32_t base = sb + (uint32_t)(s & 1) * GSTG;
        #pragma unroll
        for (int q = 0; q < 4; ++q) {
            int i = q * 256 + tid;
            int r = i >> 3, c = i & 7;
            cpasync16(base + (uint32_t)(r * (APITCH * 4) + c * 16),
                      Ab + (size_t)r * (Ec * 4) + s * 128 + c * 16);
        }
        #pragma unroll
        for (int q = 0; q < 4; ++q) {
            int i = q * 256 + tid;
            int r = i >> 5, c = i & 31;
            cpasync16(base + ASTG + (uint32_t)(r * (BPITCH * 4) + c * 16),
                      Wb + (size_t)(s * 32 + r) * (Ec * 4) + c * 16);
        }
        CP_COMMIT();
    };

    float acc[4][4][4] = {};
    fill(0);

    for (int s = 0; s < 16; ++s) {
        if (s < 15) {
            fill(s + 1);
            CP_WAIT(1);
        } else {
            CP_WAIT(0);
        }
        __syncthreads();

        const uint8_t* buf = smem + (s & 1) * GSTG;
        const uint32_t* As = (const uint32_t*)buf;
        const uint32_t* Ws = (const uint32_t*)(buf + ASTG);

        #pragma unroll
        for (int k8 = 0; k8 < 4; ++k8) {
            uint32_t a[4][4];
            #pragma unroll
            for (int mt = 0; mt < 4; ++mt) {
                int m = wm * 64 + mt * 16;
                a[mt][0] = As[(m + g    ) * APITCH + k8 * 8 + t];
                a[mt][1] = As[(m + g + 8) * APITCH + k8 * 8 + t];
                a[mt][2] = As[(m + g    ) * APITCH + k8 * 8 + t + 4];
                a[mt][3] = As[(m + g + 8) * APITCH + k8 * 8 + t + 4];
            }
            #pragma unroll
            for (int nt = 0; nt < 4; ++nt) {
                uint32_t b0 = Ws[(k8 * 8 + t    ) * BPITCH + wn * 32 + nt * 8 + g];
                uint32_t b1 = Ws[(k8 * 8 + t + 4) * BPITCH + wn * 32 + nt * 8 + g];
                #pragma unroll
                for (int mt = 0; mt < 4; ++mt)
                    mma_tf32(acc[mt][nt], a[mt][0], a[mt][1], a[mt][2], a[mt][3], b0, b1);
            }
        }
        __syncthreads();
    }

    #pragma unroll
    for (int mt = 0; mt < 4; ++mt) {
        #pragma unroll
        for (int nt = 0; nt < 4; ++nt) {
            int m = m0 + wm * 64 + mt * 16 + g;
            int n = n0 + wn * 32 + nt * 8 + 2 * t;
            float b0v = bias[n], b1v = bias[n + 1];
            float v00 = __uint_as_float(f2t((acc[mt][nt][0] + b0v) * scale));
            float v01 = __uint_as_float(f2t((acc[mt][nt][1] + b1v) * scale));
            float v10 = __uint_as_float(f2t((acc[mt][nt][2] + b0v) * scale));
            float v11 = __uint_as_float(f2t((acc[mt][nt][3] + b1v) * scale));
            *(float2*)(C + (size_t)m * Ec + n)       = make_float2(v00, v01);
            *(float2*)(C + (size_t)(m + 8) * Ec + n) = make_float2(v10, v11);
        }
    }
}

// single GEMM for output projection (fp32 out, no rounding)
__global__ __launch_bounds__(256) void gemm_tf32_o(
    const float* __restrict__ A, const float* __restrict__ W,
    const float* __restrict__ bias, float* __restrict__ C)
{
    extern __shared__ __align__(16) uint8_t smem[];
    const uint32_t sb = s2u(smem);

    const int tid  = threadIdx.x;
    const int lane = tid & 31;
    const int w    = tid >> 5;
    const int wm   = w >> 2;
    const int wn   = w & 3;
    const int g    = lane >> 2;
    const int t    = lane & 3;
    const int m0   = blockIdx.y * 128;
    const int n0   = blockIdx.x * 128;

    const char* Ab = (const char*)A + (size_t)m0 * Ec * 4;
    const char* Wb = (const char*)W + (size_t)n0 * 4;

    auto fill = [&](int s) {
        uint32_t base = sb + (uint32_t)(s & 1) * GSTG;
        #pragma unroll
        for (int q = 0; q < 4; ++q) {
            int i = q * 256 + tid;
            int r = i >> 3, c = i & 7;
            cpasync16(base + (uint32_t)(r * (APITCH * 4) + c * 16),
                      Ab + (size_t)r * (Ec * 4) + s * 128 + c * 16);
        }
        #pragma unroll
        for (int q = 0; q < 4; ++q) {
            int i = q * 256 + tid;
            int r = i >> 5, c = i & 31;
            cpasync16(base + ASTG + (uint32_t)(r * (BPITCH * 4) + c * 16),
                      Wb + (size_t)(s * 32 + r) * (Ec * 4) + c * 16);
        }
        CP_COMMIT();
    };

    float acc[4][4][4] = {};
    fill(0);

    for (int s = 0; s < 16; ++s) {
        if (s < 15) {
            fill(s + 1);
            CP_WAIT(1);
        } else {
            CP_WAIT(0);
        }
        __syncthreads();

        const uint8_t* buf = smem + (s & 1) * GSTG;
        const uint32_t* As = (const uint32_t*)buf;
        const uint32_t* Ws = (const uint32_t*)(buf + ASTG);

        #pragma unroll
        for (int k8 = 0; k8 < 4; ++k8) {
            uint32_t a[4][4];
            #pragma unroll
            for (int mt = 0; mt < 4; ++mt) {
                int m = wm * 64 + mt * 16;
                a[mt][0] = As[(m + g    ) * APITCH + k8 * 8 + t];
                a[mt][1] = As[(m + g + 8) * APITCH + k8 * 8 + t];
                a[mt][2] = As[(m + g    ) * APITCH + k8 * 8 + t + 4];
                a[mt][3] = As[(m + g + 8) * APITCH + k8 * 8 + t + 4];
            }
            #pragma unroll
            for (int nt = 0; nt < 4; ++nt) {
                uint32_t b0 = Ws[(k8 * 8 + t    ) * BPITCH + wn * 32 + nt * 8 + g];
                uint32_t b1 = Ws[(k8 * 8 + t + 4) * BPITCH + wn * 32 + nt * 8 + g];
                #pragma unroll
                for (int mt = 0; mt < 4; ++mt)
                    mma_tf32(acc[mt][nt], a[mt][0], a[mt][1], a[mt][2], a[mt][3], b0, b1);
            }
        }
        __syncthreads();
    }

    #pragma unroll
    for (int mt = 0; mt < 4; ++mt) {
        #pragma unroll
        for (int nt = 0; nt < 4; ++nt) {
            int m = m0 + wm * 64 + mt * 16 + g;
            int n = n0 + wn * 32 + nt * 8 + 2 * t;
            float b0v = bias[n], b1v = bias[n + 1];
            *(float2*)(C + (size_t)m * Ec + n) =
                make_float2(acc[mt][nt][0] + b0v, acc[mt][nt][1] + b1v);
            *(float2*)(C + (size_t)(m + 8) * Ec + n) =
                make_float2(acc[mt][nt][2] + b0v, acc[mt][nt][3] + b1v);
        }
    }
}

// ---------------------------------------------------------------------------
// Flash attention, tf32 mma — round-11 structure exactly (64 q-rows/CTA,
// 128 threads, single K/V buffer, no min-blocks cap -> ~136 regs, 3 CTA/SM).
// exp2 via raw MUFU (ex2.approx.ftz). Q/K/V tf32-pre-rounded by projections.
// Epilogue rounds context to tf32 for the output-projection GEMM.
// ---------------------------------------------------------------------------
#define QP 68
#define VP 72
#define FA_SMEM ((2 * 64 * QP + 64 * VP + 64) * 4)   // 53504 B

__global__ __launch_bounds__(128) void flash_attn_mma(
    const float* __restrict__ Q, const float* __restrict__ K,
    const float* __restrict__ V, const int* __restrict__ mask,
    float* __restrict__ Ctx)
{
    extern __shared__ uint32_t sm[];
    uint32_t* Qs = sm;                       // [64][QP]  (also Ps after preload)
    uint32_t* Ks = sm + 64 * QP;             // [64][QP]
    uint32_t* Vs = sm + 2 * 64 * QP;         // [64][VP]
    float* mneg  = (float*)(sm + 2 * 64 * QP + 64 * VP);  // [64]

    const uint32_t sbase = s2u(sm);
    const uint32_t qsb = sbase;
    const uint32_t ksb = sbase + 64 * QP * 4;
    const uint32_t vsb = sbase + 2 * 64 * QP * 4;

    const int tid  = threadIdx.x;
    const int lane = tid & 31;
    const int w    = tid >> 5;
    const int g    = lane >> 2;
    const int t    = lane & 3;
    const int b    = blockIdx.y >> 3, h = blockIdx.y & 7;
    const int m0   = blockIdx.x * 64;
    const int w16  = w * 16;

    const char* Qb = (const char*)(Q + ((size_t)b * Sq + m0) * Ec + h * Dc);
    const char* Kb = (const char*)(K + (size_t)b * Sq * Ec + h * Dc);
    const char* Vb = (const char*)(V + (size_t)b * Sq * Ec + h * Dc);
    const int*  mb = mask + b * Sq;

    // Load Q tile 64x64 via cp.async (already tf32 bit patterns)
    #pragma unroll
    for (int p = 0; p < 8; ++p) {
        int i = p * 128 + tid;
        int r = i >> 4, c = i & 15;
        cpasync16(qsb + (uint32_t)(r * (QP * 4) + c * 16),
                  Qb + (size_t)r * (Ec * 4) + c * 16);
    }
    CP_COMMIT();
    CP_WAIT(0);
    __syncthreads();

    // Preload Q A-fragments into registers (reused for all 32 kv tiles)
    uint32_t qf[8][4];
    #pragma unroll
    for (int k8 = 0; k8 < 8; ++k8) {
        qf[k8][0] = Qs[(w16 + g    ) * QP + k8 * 8 + t];
        qf[k8][1] = Qs[(w16 + g + 8) * QP + k8 * 8 + t];
        qf[k8][2] = Qs[(w16 + g    ) * QP + k8 * 8 + t + 4];
        qf[k8][3] = Qs[(w16 + g + 8) * QP + k8 * 8 + t + 4];
    }
    uint32_t* Ps = Qs;   // reuse buffer

    float o[8][4] = {};
    float mi0 = -1e30f, mi1 = -1e30f, li0 = 0.f, li1 = 0.f;

    for (int kt = 0; kt < Sq / 64; ++kt) {
        __syncthreads();   // all warps done reading Ks/Vs/Ps of prev iter
        const int n0 = kt * 64;

        // K,V tiles via cp.async (no cvt, no register round-trip)
        #pragma unroll
        for (int p = 0; p < 8; ++p) {
            int i = p * 128 + tid;
            int r = i >> 4, c = i & 15;
            size_t goff = (size_t)(n0 + r) * (Ec * 4) + c * 16;
            cpasync16(ksb + (uint32_t)(r * (QP * 4) + c * 16), Kb + goff);
            cpasync16(vsb + (uint32_t)(r * (VP * 4) + c * 16), Vb + goff);
        }
        CP_COMMIT();
        CP_WAIT(0);
        if (tid < 64) mneg[tid] = (-1e9f * LOG2E) * (float)mb[n0 + tid];
        __syncthreads();

        // ---- S = Q K^T (log2e domain), 16x64 per warp ----
        float s[8][4] = {};
        #pragma unroll
        for (int k8 = 0; k8 < 8; ++k8) {
            #pragma unroll
            for (int nt = 0; nt < 8; ++nt) {
                uint32_t b0 = Ks[(nt * 8 + g) * QP + k8 * 8 + t];
                uint32_t b1 = Ks[(nt * 8 + g) * QP + k8 * 8 + t + 4];
                mma_tf32(s[nt], qf[k8][0], qf[k8][1], qf[k8][2], qf[k8][3], b0, b1);
            }
        }
        #pragma unroll
        for (int nt = 0; nt < 8; ++nt) {
            float2 mv = *(float2*)&mneg[nt * 8 + 2 * t];
            s[nt][0] += mv.x; s[nt][1] += mv.y;
            s[nt][2] += mv.x; s[nt][3] += mv.y;
        }

        // ---- online softmax (rows g and g+8; 4 threads per row) ----
        float mx0 = -1e30f, mx1 = -1e30f;
        #pragma unroll
        for (int nt = 0; nt < 8; ++nt) {
            mx0 = fmaxf(mx0, fmaxf(s[nt][0], s[nt][1]));
            mx1 = fmaxf(mx1, fmaxf(s[nt][2], s[nt][3]));
        }
        mx0 = fmaxf(mx0, __shfl_xor_sync(0xffffffffu, mx0, 1));
        mx0 = fmaxf(mx0, __shfl_xor_sync(0xffffffffu, mx0, 2));
        mx1 = fmaxf(mx1, __shfl_xor_sync(0xffffffffu, mx1, 1));
        mx1 = fmaxf(mx1, __shfl_xor_sync(0xffffffffu, mx1, 2));

        float mn0 = fmaxf(mi0, mx0), mn1 = fmaxf(mi1, mx1);
        float al0 = ex2(mi0 - mn0), al1 = ex2(mi1 - mn1);
        float sum0 = 0.f, sum1 = 0.f;
        #pragma unroll
        for (int nt = 0; nt < 8; ++nt) {
            s[nt][0] = ex2(s[nt][0] - mn0);
            s[nt][1] = ex2(s[nt][1] - mn0);
            s[nt][2] = ex2(s[nt][2] - mn1);
            s[nt][3] = ex2(s[nt][3] - mn1);
            sum0 += s[nt][0] + s[nt][1];
            sum1 += s[nt][2] + s[nt][3];
        }
        sum0 += __shfl_xor_sync(0xffffffffu, sum0, 1);
        sum0 += __shfl_xor_sync(0xffffffffu, sum0, 2);
        sum1 += __shfl_xor_sync(0xffffffffu, sum1, 1);
        sum1 += __shfl_xor_sync(0xffffffffu, sum1, 2);
        li0 = li0 * al0 + sum0;  mi0 = mn0;
        li1 = li1 * al1 + sum1;  mi1 = mn1;
        #pragma unroll
        for (int dt = 0; dt < 8; ++dt) {
            o[dt][0] *= al0; o[dt][1] *= al0;
            o[dt][2] *= al1; o[dt][3] *= al1;
        }

        // ---- store P (tf32) into Ps; each warp owns its own 16 rows ----
        #pragma unroll
        for (int nt = 0; nt < 8; ++nt) {
            *(uint2*)&Ps[(w16 + g    ) * QP + nt * 8 + 2 * t] =
                make_uint2(f2t(s[nt][0]), f2t(s[nt][1]));
            *(uint2*)&Ps[(w16 + g + 8) * QP + nt * 8 + 2 * t] =
                make_uint2(f2t(s[nt][2]), f2t(s[nt][3]));
        }
        __syncwarp();

        // ---- O += P @ V ----
        #pragma unroll
        for (int k8 = 0; k8 < 8; ++k8) {
            uint32_t a0 = Ps[(w16 + g    ) * QP + k8 * 8 + t];
            uint32_t a1 = Ps[(w16 + g + 8) * QP + k8 * 8 + t];
            uint32_t a2 = Ps[(w16 + g    ) * QP + k8 * 8 + t + 4];
            uint32_t a3 = Ps[(w16 + g + 8) * QP + k8 * 8 + t + 4];
            #pragma unroll
            for (int dt = 0; dt < 8; ++dt) {
                uint32_t b0 = Vs[(k8 * 8 + t    ) * VP + dt * 8 + g];
                uint32_t b1 = Vs[(k8 * 8 + t + 4) * VP + dt * 8 + g];
                mma_tf32(o[dt], a0, a1, a2, a3, b0, b1);
            }
        }
    }

    // Epilogue: normalize, round to tf32 (feeds output-proj GEMM), write
    float inv0 = 1.f / li0, inv1 = 1.f / li1;
    float* Cb = Ctx + ((size_t)b * Sq + m0 + w16) * Ec + h * Dc;
    #pragma unroll
    for (int dt = 0; dt < 8; ++dt) {
        int n = dt * 8 + 2 * t;
        *(uint2*)(Cb + (size_t)g * Ec + n) =
            make_uint2(f2t(o[dt][0] * inv0), f2t(o[dt][1] * inv0));
        *(uint2*)(Cb + (size_t)(g + 8) * Ec + n) =
            make_uint2(f2t(o[dt][2] * inv1), f2t(o[dt][3] * inv1));
    }
}

// ---------------------------------------------------------------------------
// Host launcher
// ---------------------------------------------------------------------------
extern "C" void kernel_launch(void* const* d_in, const int* in_sizes, int n_in,
                              void* d_out, int out_size)
{
    const float* value = (const float*)d_in[0];
    const float* key   = (const float*)d_in[1];
    const float* query = (const float*)d_in[2];
    const int*   mask  = (const int*)d_in[3];
    const float* wq = (const float*)d_in[4];
    const float* bq = (const float*)d_in[5];
    const float* wk = (const float*)d_in[6];
    const float* bk = (const float*)d_in[7];
    const float* wv = (const float*)d_in[8];
    const float* bv = (const float*)d_in[9];
    const float* wo = (const float*)d_in[10];
    const float* bo = (const float*)d_in[11];
    float* out = (float*)d_out;

    float *Qp, *Kp, *Vp, *Cp, *T3p, *WT4p;
    cudaGetSymbolAddress((void**)&Qp, g_Q);
    cudaGetSymbolAddress((void**)&Kp, g_K);
    cudaGetSymbolAddress((void**)&Vp, g_V);
    cudaGetSymbolAddress((void**)&Cp, g_C);
    cudaGetSymbolAddress((void**)&T3p, g_T3);
    cudaGetSymbolAddress((void**)&WT4p, g_WT4);

    cudaFuncSetAttribute(flash_attn_mma, cudaFuncAttributeMaxDynamicSharedMemorySize,
                         FA_SMEM);
    cudaFuncSetAttribute(gemm_tf32_qkv, cudaFuncAttributeMaxDynamicSharedMemorySize,
                         GSMEM);
    cudaFuncSetAttribute(gemm_tf32_o, cudaFuncAttributeMaxDynamicSharedMemorySize,
                         GSMEM);

    const int n4A = Mrows * Ec / 4;     // 2,097,152
    const int n4W = Ec * Ec / 4;        // 65,536

    // tf32-round all operands (z order matches gemm: q, k, v)
    conv3<<<3 * n4A / 256, 256>>>(query, key, value, T3p, n4A);
    convW4<<<4 * n4W / 256, 256>>>(wq, wk, wv, wo, WT4p, n4W);

    // batched Q/K/V projections (Q folds 0.125*log2e; outputs tf32-rounded)
    gemm_tf32_qkv<<<dim3(Ec / 128, Mrows / 128, 3), 256, GSMEM>>>(
        T3p, WT4p, bq, bk, bv, Qp, Kp, Vp);

    // attention: 64 q-rows per CTA, grid (32, 64)
    flash_attn_mma<<<dim3(Sq / 64, Bc * Hc), 128, FA_SMEM>>>(Qp, Kp, Vp, mask, Cp);

    // output projection (fp32 output)
    gemm_tf32_o<<<dim3(Ec / 128, Mrows / 128), 256, GSMEM>>>(
        Cp, WT4p + (size_t)3 * Ec * Ec, bo, out);
}